// round 12
// baseline (speedup 1.0000x reference)
#include <cuda_runtime.h>
#include <cuda_fp16.h>
#include <math.h>
#include <stdint.h>

#define NB 4
#define NC 512
#define NT 1024
#define NHEADS 8
#define NHD 64
#define EPS_IN 1e-5f
#define QT 32
#define CH 64

// ---------------- device scratch ----------------
__device__ __half g_w16[4 * NC * NC];                      // wq,wk,wv,wproj fp16
__device__ __half g_xT[NB * NT * NC];                      // x transposed [b][t][c]
__device__ __half g_qT[NB * NT * NC];
__device__ __half g_kT[NB * NT * NC];
__device__ __half g_vh[NB * NC * NT];                      // v [b][c][t]
__device__ float g_oacc[NB * NHEADS * NT * NHD];           // unnormalized PV accum [bh][q][d]
__device__ float g_l[NB * NHEADS * NT];                    // softmax denominators
__device__ float g_vsum[NB * NC];
__device__ float g_rowsq[NB * NHEADS * NT];
__device__ float g_alpha[32];
__device__ float g_betac[32];

__device__ __forceinline__ void mma16h(float* c, const uint32_t* a, const uint32_t* b) {
    asm volatile("mma.sync.aligned.m16n8k16.row.col.f32.f16.f16.f32 "
        "{%0,%1,%2,%3}, {%4,%5,%6,%7}, {%8,%9}, {%0,%1,%2,%3};\n"
        : "+f"(c[0]), "+f"(c[1]), "+f"(c[2]), "+f"(c[3])
        : "r"(a[0]), "r"(a[1]), "r"(a[2]), "r"(a[3]), "r"(b[0]), "r"(b[1]));
}
__device__ __forceinline__ float ex2f(float x) {
    float r;
    asm("ex2.approx.ftz.f32 %0, %1;" : "=f"(r) : "f"(x));
    return r;
}

// ============ prep: weights -> fp16 ============
__global__ __launch_bounds__(256) void prep_w(const float* __restrict__ wq,
                                              const float* __restrict__ wk,
                                              const float* __restrict__ wv,
                                              const float* __restrict__ wp) {
    int idx = blockIdx.x * 256 + threadIdx.x;
    int which = idx >> 18, off = idx & 262143;
    const float* s = (which == 0) ? wq : (which == 1) ? wk : (which == 2) ? wv : wp;
    g_w16[idx] = __float2half(s[off]);
}

// ============ prep: xT[b][t][c] fp16 ============
__global__ __launch_bounds__(256) void prep_x(const float* __restrict__ x) {
    __shared__ float tile[32][33];
    int tx = threadIdx.x, ty = threadIdx.y;
    int tBase = blockIdx.x * 32, cBase = blockIdx.y * 32, b = blockIdx.z;
    const float* X = x + (size_t)b * NC * NT;
#pragma unroll
    for (int p = 0; p < 4; p++)
        tile[ty + 8 * p][tx] = X[(size_t)(cBase + ty + 8 * p) * NT + tBase + tx];
    __syncthreads();
    __half* dst = g_xT + (size_t)b * NT * NC;
#pragma unroll
    for (int p = 0; p < 4; p++)
        dst[(size_t)(tBase + ty + 8 * p) * NC + cBase + tx] = __float2half(tile[tx][ty + 8 * p]);
}

// ============ Kernel 1: QKV fp16 ============
__global__ __launch_bounds__(256) void qkv_f16() {
    int z = blockIdx.z;
    int b = z / 3, which = z - b * 3;
    const __half* W = g_w16 + (size_t)which * NC * NC;
    const __half* X = g_xT + (size_t)b * NT * NC;

    int oBase = blockIdx.y * 128;
    int tBase = blockIdx.x * 128;

    __shared__ union {
        struct { uint32_t A[128][20]; uint32_t B[128][20]; } ab;
        unsigned short st[128][136];
    } smu;

    int tid = threadIdx.x, lane = tid & 31, wid = tid >> 5;
    int wm = wid >> 2, wn = wid & 3;
    int lr = lane >> 2, lk = lane & 3;

    float acc[4][4][4];
#pragma unroll
    for (int mi = 0; mi < 4; mi++)
#pragma unroll
        for (int nj = 0; nj < 4; nj++)
#pragma unroll
            for (int ci = 0; ci < 4; ci++) acc[mi][nj][ci] = 0.f;

    for (int k0 = 0; k0 < NC; k0 += 32) {
#pragma unroll
        for (int i = 0; i < 2; i++) {
            int idx = tid + i * 256;
            int row = idx >> 2, uu = idx & 3;
            *(uint4*)&smu.ab.A[row][uu * 4] =
                *(const uint4*)&W[(size_t)(oBase + row) * NC + k0 + uu * 8];
            *(uint4*)&smu.ab.B[row][uu * 4] =
                *(const uint4*)&X[(size_t)(tBase + row) * NC + k0 + uu * 8];
        }
        __syncthreads();
#pragma unroll
        for (int ci = 0; ci < 2; ci++) {
            int kc = ci * 8;
            uint32_t af[4][4], bf[4][2];
#pragma unroll
            for (int mi = 0; mi < 4; mi++) {
                int m0 = wm * 64 + mi * 16 + lr;
                af[mi][0] = smu.ab.A[m0][kc + lk];
                af[mi][1] = smu.ab.A[m0 + 8][kc + lk];
                af[mi][2] = smu.ab.A[m0][kc + lk + 4];
                af[mi][3] = smu.ab.A[m0 + 8][kc + lk + 4];
            }
#pragma unroll
            for (int nj = 0; nj < 4; nj++) {
                int n0 = wn * 32 + nj * 8 + lr;
                bf[nj][0] = smu.ab.B[n0][kc + lk];
                bf[nj][1] = smu.ab.B[n0][kc + lk + 4];
            }
#pragma unroll
            for (int mi = 0; mi < 4; mi++)
#pragma unroll
                for (int nj = 0; nj < 4; nj++) mma16h(acc[mi][nj], af[mi], bf[nj]);
        }
        __syncthreads();
    }

    if (which == 2) {
        __half* vh = g_vh + (size_t)b * NC * NT;
#pragma unroll
        for (int mi = 0; mi < 4; mi++) {
            int r = oBase + wm * 64 + mi * 16 + lr;
#pragma unroll
            for (int nj = 0; nj < 4; nj++) {
                int cc = tBase + wn * 32 + nj * 8 + lk * 2;
                *(__half2*)&vh[(size_t)r * NT + cc] =
                    __floats2half2_rn(acc[mi][nj][0], acc[mi][nj][1]);
                *(__half2*)&vh[(size_t)(r + 8) * NT + cc] =
                    __floats2half2_rn(acc[mi][nj][2], acc[mi][nj][3]);
            }
        }
    } else {
        __half* dst = ((which == 0) ? g_qT : g_kT) + (size_t)b * NT * NC;
#pragma unroll
        for (int mi = 0; mi < 4; mi++) {
            int r = wm * 64 + mi * 16 + lr;
#pragma unroll
            for (int nj = 0; nj < 4; nj++) {
                int cc = wn * 32 + nj * 8 + lk * 2;
                smu.st[cc][r]         = __half_as_ushort(__float2half(acc[mi][nj][0]));
                smu.st[cc + 1][r]     = __half_as_ushort(__float2half(acc[mi][nj][1]));
                smu.st[cc][r + 8]     = __half_as_ushort(__float2half(acc[mi][nj][2]));
                smu.st[cc + 1][r + 8] = __half_as_ushort(__float2half(acc[mi][nj][3]));
            }
        }
        __syncthreads();
        int row = tid >> 1, ub = (tid & 1) * 8;
#pragma unroll
        for (int j = 0; j < 8; j++) {
            *(uint4*)&dst[(size_t)(tBase + row) * NC + oBase + (ub + j) * 8] =
                *(const uint4*)&smu.st[row][(ub + j) * 8];
        }
    }
}

// ============ Kernel 2: fully fused QK -> mix -> softmax -> PV ============
__global__ __launch_bounds__(256) void fa(const float* __restrict__ w_head) {
    extern __shared__ char smc[];
    __half* QsH = (__half*)smc;                        // 8h x 32q x 72d
    __half* KVH = (__half*)(smc + 36864);              // K / V region
    float*  SsF = (float*)(smc + 110592);              // 8h x 32q x 68t
    __half* PsH = (__half*)(smc + 180224);             // 8g x 32q x 72t
    float*  Scs = (float*)(smc + 217088);              // 8g x 32q
    float*  whs = (float*)(smc + 218112);              // 64
    uint32_t* QsU = (uint32_t*)QsH;
    uint32_t* KVU = (uint32_t*)KVH;
    uint32_t* PsU = (uint32_t*)PsH;

    int b = blockIdx.y;
    int qBase = blockIdx.x * QT;
    int tid = threadIdx.x, lane = tid & 31, wid = tid >> 5;
    int lr = lane >> 2, lk = lane & 3;
    int qD = tid >> 3, s8 = (tid & 7) * 8;

    if (tid < 64) whs[tid] = w_head[tid] * 1.4426950408889634f;

    {
        const __half* Qsrc = g_qT + ((size_t)b * NT + qBase) * NC;
        __half2 sc8 = __float2half2_rn(0.125f);
#pragma unroll
        for (int i = 0; i < 8; i++) {
            int idx = tid + i * 256;
            int q = idx >> 6, u = idx & 63;
            uint4 v = *(const uint4*)&Qsrc[q * NC + u * 8];
            __half2* pv2 = (__half2*)&v;
            pv2[0] = __hmul2(pv2[0], sc8); pv2[1] = __hmul2(pv2[1], sc8);
            pv2[2] = __hmul2(pv2[2], sc8); pv2[3] = __hmul2(pv2[3], sc8);
            *(uint4*)&QsH[(u >> 3) * 2304 + q * 72 + (u & 7) * 8] = v;
        }
    }

    float m[8], l[8], s2[8];
#pragma unroll
    for (int g = 0; g < 8; g++) { m[g] = -1e30f; l[g] = 0.f; s2[g] = 0.f; }

    float pv[2][8][4];
#pragma unroll
    for (int mi = 0; mi < 2; mi++)
#pragma unroll
        for (int nj = 0; nj < 8; nj++)
#pragma unroll
            for (int ci = 0; ci < 4; ci++) pv[mi][nj][ci] = 0.f;

    const __half* Ksrc = g_kT + (size_t)b * NT * NC;
    const __half* Vsrc = g_vh + (size_t)b * NC * NT;

    __syncthreads();

    for (int c0 = 0; c0 < NT; c0 += CH) {
#pragma unroll
        for (int i = 0; i < 16; i++) {
            int idx = tid + i * 256;
            int t = idx >> 6, u = idx & 63;
            uint4 v = *(const uint4*)&Ksrc[(size_t)(c0 + t) * NC + u * 8];
            *(uint4*)&KVH[(u >> 3) * 4608 + t * 72 + (u & 7) * 8] = v;
        }
        __syncthreads();

        {
            int h = wid;
            float sacc[2][8][4];
#pragma unroll
            for (int mi = 0; mi < 2; mi++)
#pragma unroll
                for (int nj = 0; nj < 8; nj++)
#pragma unroll
                    for (int ci = 0; ci < 4; ci++) sacc[mi][nj][ci] = 0.f;
#pragma unroll
            for (int ks = 0; ks < 4; ks++) {
                int kb = ks * 8;
                uint32_t af[2][4], bf[8][2];
#pragma unroll
                for (int mi = 0; mi < 2; mi++) {
                    int m0 = mi * 16 + lr;
                    af[mi][0] = QsU[h * 1152 + m0 * 36 + kb + lk];
                    af[mi][1] = QsU[h * 1152 + (m0 + 8) * 36 + kb + lk];
                    af[mi][2] = QsU[h * 1152 + m0 * 36 + kb + lk + 4];
                    af[mi][3] = QsU[h * 1152 + (m0 + 8) * 36 + kb + lk + 4];
                }
#pragma unroll
                for (int nj = 0; nj < 8; nj++) {
                    int n0 = nj * 8 + lr;
                    bf[nj][0] = KVU[h * 2304 + n0 * 36 + kb + lk];
                    bf[nj][1] = KVU[h * 2304 + n0 * 36 + kb + lk + 4];
                }
#pragma unroll
                for (int mi = 0; mi < 2; mi++)
#pragma unroll
                    for (int nj = 0; nj < 8; nj++) mma16h(sacc[mi][nj], af[mi], bf[nj]);
            }
            float* Sh = SsF + wid * 2176;
#pragma unroll
            for (int mi = 0; mi < 2; mi++) {
                int r0 = mi * 16 + lr;
#pragma unroll
                for (int nj = 0; nj < 8; nj++) {
                    int cc = nj * 8 + lk * 2;
                    *(float2*)&Sh[r0 * 68 + cc] = make_float2(sacc[mi][nj][0], sacc[mi][nj][1]);
                    *(float2*)&Sh[(r0 + 8) * 68 + cc] = make_float2(sacc[mi][nj][2], sacc[mi][nj][3]);
                }
            }
        }
        __syncthreads();

        {
            unsigned long long xh[8][4];
            const float* Sq = SsF + qD * 68 + s8;
#pragma unroll
            for (int h = 0; h < 8; h++) {
                const double2* dp = (const double2*)(Sq + h * 2176);
                double2 d0 = dp[0], d1 = dp[1];
                xh[h][0] = __double_as_longlong(d0.x);
                xh[h][1] = __double_as_longlong(d0.y);
                xh[h][2] = __double_as_longlong(d1.x);
                xh[h][3] = __double_as_longlong(d1.y);
            }
#pragma unroll
            for (int g = 0; g < 8; g++) {
                unsigned long long a0 = 0, a1 = 0, a2 = 0, a3 = 0;
#pragma unroll
                for (int h = 0; h < 8; h++) {
                    float w = whs[g * 8 + h];
                    unsigned long long w2;
                    asm("mov.b64 %0, {%1, %1};" : "=l"(w2) : "f"(w));
                    asm("fma.rn.f32x2 %0, %1, %2, %0;" : "+l"(a0) : "l"(w2), "l"(xh[h][0]));
                    asm("fma.rn.f32x2 %0, %1, %2, %0;" : "+l"(a1) : "l"(w2), "l"(xh[h][1]));
                    asm("fma.rn.f32x2 %0, %1, %2, %0;" : "+l"(a2) : "l"(w2), "l"(xh[h][2]));
                    asm("fma.rn.f32x2 %0, %1, %2, %0;" : "+l"(a3) : "l"(w2), "l"(xh[h][3]));
                }
                float mg[8];
                asm("mov.b64 {%0, %1}, %2;" : "=f"(mg[0]), "=f"(mg[1]) : "l"(a0));
                asm("mov.b64 {%0, %1}, %2;" : "=f"(mg[2]), "=f"(mg[3]) : "l"(a1));
                asm("mov.b64 {%0, %1}, %2;" : "=f"(mg[4]), "=f"(mg[5]) : "l"(a2));
                asm("mov.b64 {%0, %1}, %2;" : "=f"(mg[6]), "=f"(mg[7]) : "l"(a3));

                float cm = fmaxf(fmaxf(fmaxf(mg[0], mg[1]), fmaxf(mg[2], mg[3])),
                                 fmaxf(fmaxf(mg[4], mg[5]), fmaxf(mg[6], mg[7])));
                cm = fmaxf(cm, __shfl_xor_sync(0xffffffffu, cm, 1));
                cm = fmaxf(cm, __shfl_xor_sync(0xffffffffu, cm, 2));
                cm = fmaxf(cm, __shfl_xor_sync(0xffffffffu, cm, 4));
                float nm = fmaxf(m[g], cm);
                float sc = ex2f(m[g] - nm);
                m[g] = nm;
                float e0 = ex2f(mg[0] - nm), e1 = ex2f(mg[1] - nm);
                float e2 = ex2f(mg[2] - nm), e3 = ex2f(mg[3] - nm);
                float e4 = ex2f(mg[4] - nm), e5 = ex2f(mg[5] - nm);
                float e6 = ex2f(mg[6] - nm), e7 = ex2f(mg[7] - nm);
                float cl = ((e0 + e1) + (e2 + e3)) + ((e4 + e5) + (e6 + e7));
                float cq = ((e0 * e0 + e1 * e1) + (e2 * e2 + e3 * e3)) +
                           ((e4 * e4 + e5 * e5) + (e6 * e6 + e7 * e7));
                l[g] = l[g] * sc + cl;
                s2[g] = s2[g] * (sc * sc) + cq;
                __half2 p0 = __floats2half2_rn(e0, e1);
                __half2 p1 = __floats2half2_rn(e2, e3);
                __half2 p2 = __floats2half2_rn(e4, e5);
                __half2 p3 = __floats2half2_rn(e6, e7);
                uint4 u;
                u.x = *(uint32_t*)&p0; u.y = *(uint32_t*)&p1;
                u.z = *(uint32_t*)&p2; u.w = *(uint32_t*)&p3;
                *(uint4*)&PsH[g * 2304 + qD * 72 + s8] = u;
                if ((tid & 7) == 0) Scs[g * 32 + qD] = sc;
            }
        }
#pragma unroll
        for (int i = 0; i < 16; i++) {
            int idx = tid + i * 256;
            int c = idx >> 3, seg = idx & 7;
            uint4 v = *(const uint4*)&Vsrc[(size_t)c * NT + c0 + seg * 8];
            *(uint4*)&KVH[c * 72 + seg * 8] = v;
        }
        __syncthreads();

        {
            int g = wid;
            float s00 = Scs[g * 32 + lr],      s01 = Scs[g * 32 + lr + 8];
            float s10 = Scs[g * 32 + 16 + lr], s11 = Scs[g * 32 + 24 + lr];
#pragma unroll
            for (int nj = 0; nj < 8; nj++) {
                pv[0][nj][0] *= s00; pv[0][nj][1] *= s00;
                pv[0][nj][2] *= s01; pv[0][nj][3] *= s01;
                pv[1][nj][0] *= s10; pv[1][nj][1] *= s10;
                pv[1][nj][2] *= s11; pv[1][nj][3] *= s11;
            }
#pragma unroll
            for (int ks = 0; ks < 4; ks++) {
                int kb = ks * 8;
                uint32_t af[2][4], bf[8][2];
#pragma unroll
                for (int mi = 0; mi < 2; mi++) {
                    int m0 = mi * 16 + lr;
                    af[mi][0] = PsU[g * 1152 + m0 * 36 + kb + lk];
                    af[mi][1] = PsU[g * 1152 + (m0 + 8) * 36 + kb + lk];
                    af[mi][2] = PsU[g * 1152 + m0 * 36 + kb + lk + 4];
                    af[mi][3] = PsU[g * 1152 + (m0 + 8) * 36 + kb + lk + 4];
                }
#pragma unroll
                for (int nj = 0; nj < 8; nj++) {
                    int n0 = g * 64 + nj * 8 + lr;
                    bf[nj][0] = KVU[n0 * 36 + kb + lk];
                    bf[nj][1] = KVU[n0 * 36 + kb + lk + 4];
                }
#pragma unroll
                for (int mi = 0; mi < 2; mi++)
#pragma unroll
                    for (int nj = 0; nj < 8; nj++) mma16h(pv[mi][nj], af[mi], bf[nj]);
            }
        }
        __syncthreads();
    }

#pragma unroll
    for (int g = 0; g < 8; g++) {
        float lv = l[g], sv = s2[g];
        lv += __shfl_xor_sync(0xffffffffu, lv, 1);
        sv += __shfl_xor_sync(0xffffffffu, sv, 1);
        lv += __shfl_xor_sync(0xffffffffu, lv, 2);
        sv += __shfl_xor_sync(0xffffffffu, sv, 2);
        lv += __shfl_xor_sync(0xffffffffu, lv, 4);
        sv += __shfl_xor_sync(0xffffffffu, sv, 4);
        if ((tid & 7) == 0) {
            int r = (b * 8 + g) * NT + qBase + qD;
            g_l[r] = lv;
            g_rowsq[r] = sv / (lv * lv);
        }
    }
    {
        int g = wid;
        float* Op = g_oacc + ((size_t)(b * 8 + g) * NT + qBase) * NHD;
#pragma unroll
        for (int mi = 0; mi < 2; mi++) {
            int r0 = mi * 16 + lr;
#pragma unroll
            for (int nj = 0; nj < 8; nj++) {
                int cc = nj * 8 + lk * 2;
                *(float2*)&Op[(size_t)r0 * NHD + cc] = make_float2(pv[mi][nj][0], pv[mi][nj][1]);
                *(float2*)&Op[(size_t)(r0 + 8) * NHD + cc] = make_float2(pv[mi][nj][2], pv[mi][nj][3]);
            }
        }
    }
}

// ============ Kernel 4: vsum — one warp per row, MLP 4 ============
__global__ __launch_bounds__(256) void vsum2() {
    int wid = threadIdx.x >> 5, lane = threadIdx.x & 31;
    int row = blockIdx.x * 8 + wid;
    const uint4* p = (const uint4*)(g_vh + (size_t)row * NT);
    uint4 u0 = p[lane], u1 = p[lane + 32], u2 = p[lane + 64], u3 = p[lane + 96];
    float s = 0.f;
#pragma unroll
    for (int k = 0; k < 4; k++) {
        uint4 u = (k == 0) ? u0 : (k == 1) ? u1 : (k == 2) ? u2 : u3;
        const __half2* h2 = (const __half2*)&u;
#pragma unroll
        for (int j = 0; j < 4; j++) {
            float2 f = __half22float2(h2[j]);
            s += f.x + f.y;
        }
    }
#pragma unroll
    for (int o = 16; o > 0; o >>= 1) s += __shfl_xor_sync(0xffffffffu, s, o);
    if (lane == 0) g_vsum[row] = s;
}

// ============ Kernel 5: finalize InstanceNorm params ============
__global__ __launch_bounds__(256) void finalize_kernel(const float* __restrict__ gamma,
                                                       const float* __restrict__ beta) {
    __shared__ float sbuf[8];
    int grp = blockIdx.x;
    float s = 0.f;
    for (int i = threadIdx.x; i < NT; i += 256) s += g_rowsq[grp * NT + i];
    int lane = threadIdx.x & 31, w = threadIdx.x >> 5;
#pragma unroll
    for (int o = 16; o > 0; o >>= 1) s += __shfl_xor_sync(0xffffffffu, s, o);
    if (lane == 0) sbuf[w] = s;
    __syncthreads();
    if (threadIdx.x == 0) {
        float sumsq = 0.f;
        for (int i = 0; i < 8; i++) sumsq += sbuf[i];
        const float invN = 1.f / (1024.f * 1024.f);
        float mean = 1.f / 1024.f;
        float var = sumsq * invN - mean * mean;
        int h = grp & 7;
        float alpha = gamma[h] * rsqrtf(var + EPS_IN);
        g_alpha[grp] = alpha;
        g_betac[grp] = beta[h] - alpha * mean;
    }
}

// ============ Kernel 6: projection with fused normalize epilogue-on-load ============
// mid flat index t*512+c maps to: h = t>>7, q = (t&127)*8 + (c>>6), d = c&63.
__global__ __launch_bounds__(256) void proj_fused(const float* __restrict__ b_proj,
                                                  float* __restrict__ outF) {
    int b = blockIdx.z;
    int coBase = blockIdx.y * 128;
    int tBase = blockIdx.x * 128;
    const __half* W = g_w16 + (size_t)3 * NC * NC;

    __shared__ uint32_t As[128][20];
    __shared__ uint32_t Bs[128][20];

    int tid = threadIdx.x, lane = tid & 31, wid = tid >> 5;
    int wm = wid >> 2, wn = wid & 3;
    int lr = lane >> 2, lk = lane & 3;

    float acc[4][4][4];
#pragma unroll
    for (int mi = 0; mi < 4; mi++)
#pragma unroll
        for (int nj = 0; nj < 4; nj++)
#pragma unroll
            for (int ci = 0; ci < 4; ci++) acc[mi][nj][ci] = 0.f;

    for (int k0 = 0; k0 < NC; k0 += 32) {
        int chi = k0 >> 6;          // c high bits (q low part), constant in slab
        int dBase = k0 & 63;        // d base, constant in slab
#pragma unroll
        for (int i = 0; i < 2; i++) {
            int idx = tid + i * 256;
            int row = idx >> 2, uu = idx & 3;
            *(uint4*)&As[row][uu * 4] =
                *(const uint4*)&W[(size_t)(coBase + row) * NC + k0 + uu * 8];
            int t = tBase + row;
            int bh = b * 8 + (t >> 7);                 // head from t
            int q  = ((t & 127) << 3) + chi;           // attention row
            int d0 = dBase + uu * 8;
            float alpha = g_alpha[bh], bc = g_betac[bh];
            const float* Op = &g_oacc[((size_t)bh * NT + q) * NHD + d0];
            float4 o0 = *(const float4*)Op;
            float4 o1 = *(const float4*)(Op + 4);
            float ail = alpha / g_l[bh * NT + q];
            float4 v0 = *(const float4*)&g_vsum[bh * NHD + d0];
            float4 v1 = *(const float4*)&g_vsum[bh * NHD + d0 + 4];
            __half2 h0 = __floats2half2_rn(ail * o0.x + bc * v0.x, ail * o0.y + bc * v0.y);
            __half2 h1 = __floats2half2_rn(ail * o0.z + bc * v0.z, ail * o0.w + bc * v0.w);
            __half2 h2 = __floats2half2_rn(ail * o1.x + bc * v1.x, ail * o1.y + bc * v1.y);
            __half2 h3 = __floats2half2_rn(ail * o1.z + bc * v1.z, ail * o1.w + bc * v1.w);
            uint4 u;
            u.x = *(uint32_t*)&h0; u.y = *(uint32_t*)&h1;
            u.z = *(uint32_t*)&h2; u.w = *(uint32_t*)&h3;
            *(uint4*)&Bs[row][uu * 4] = u;
        }
        __syncthreads();
#pragma unroll
        for (int ci = 0; ci < 2; ci++) {
            int kc = ci * 8;
            uint32_t af[4][4], bf[4][2];
#pragma unroll
            for (int mi = 0; mi < 4; mi++) {
                int m0 = wm * 64 + mi * 16 + lr;
                af[mi][0] = As[m0][kc + lk];
                af[mi][1] = As[m0 + 8][kc + lk];
                af[mi][2] = As[m0][kc + lk + 4];
                af[mi][3] = As[m0 + 8][kc + lk + 4];
            }
#pragma unroll
            for (int nj = 0; nj < 4; nj++) {
                int n0 = wn * 32 + nj * 8 + lr;
                bf[nj][0] = Bs[n0][kc + lk];
                bf[nj][1] = Bs[n0][kc + lk + 4];
            }
#pragma unroll
            for (int mi = 0; mi < 4; mi++)
#pragma unroll
                for (int nj = 0; nj < 4; nj++) mma16h(acc[mi][nj], af[mi], bf[nj]);
        }
        __syncthreads();
    }
#pragma unroll
    for (int mi = 0; mi < 4; mi++) {
        int co = coBase + wm * 64 + mi * 16 + lr;
        float bias0 = b_proj[co], bias1 = b_proj[co + 8];
        float* op0 = outF + (size_t)b * NC * NT + (size_t)co * NT;
        float* op1 = op0 + (size_t)8 * NT;
#pragma unroll
        for (int nj = 0; nj < 4; nj++) {
            int cc = tBase + wn * 32 + nj * 8 + lk * 2;
            *(float2*)&op0[cc] = make_float2(acc[mi][nj][0] + bias0, acc[mi][nj][1] + bias0);
            *(float2*)&op1[cc] = make_float2(acc[mi][nj][2] + bias1, acc[mi][nj][3] + bias1);
        }
    }
}

// ---------------- launch ----------------
extern "C" void kernel_launch(void* const* d_in, const int* in_sizes, int n_in,
                              void* d_out, int out_size) {
    (void)in_sizes; (void)n_in; (void)out_size;
    const float* x        = (const float*)d_in[0];
    const float* w_q      = (const float*)d_in[1];
    const float* w_k      = (const float*)d_in[2];
    const float* w_v      = (const float*)d_in[3];
    const float* w_head   = (const float*)d_in[4];
    const float* in_gamma = (const float*)d_in[5];
    const float* in_beta  = (const float*)d_in[6];
    const float* w_proj   = (const float*)d_in[7];
    const float* b_proj   = (const float*)d_in[8];
    float* outF = (float*)d_out;

    const int FA_SMEM = 218368;
    cudaFuncSetAttribute(fa, cudaFuncAttributeMaxDynamicSharedMemorySize, FA_SMEM);

    prep_w<<<4096, 256>>>(w_q, w_k, w_v, w_proj);
    prep_x<<<dim3(32, 16, 4), dim3(32, 8)>>>(x);
    qkv_f16<<<dim3(8, 4, 12), 256>>>();
    fa<<<dim3(NT / QT, NB), 256, FA_SMEM>>>(w_head);      // 4th launch -> ncu target
    vsum2<<<256, 256>>>();
    finalize_kernel<<<32, 256>>>(in_gamma, in_beta);
    proj_fused<<<dim3(8, 4, 4), 256>>>(b_proj, outF);
}